// round 11
// baseline (speedup 1.0000x reference)
#include <cuda_runtime.h>
#include <math.h>
#include <stdint.h>

#define Bn 64
#define Tn 512
#define Hn 768
#define Ln 25

__device__ __align__(16) float g_eem  [Bn * Tn * Ln];
__device__ __align__(16) float g_emtag[Bn * Tn];
__device__ __align__(16) float g_H    [Bn * 256 * 700];  // Ht[b][s][j][28], 45.9MB
__device__ float g_llh[Bn];
__device__ int   g_cnt;

typedef unsigned long long ull;

__device__ __forceinline__ ull fma2(ull a, ull b, ull c) {
    ull d; asm("fma.rn.f32x2 %0, %1, %2, %3;" : "=l"(d) : "l"(a), "l"(b), "l"(c)); return d;
}
__device__ __forceinline__ ull mul2(ull a, ull b) {
    ull d; asm("mul.rn.f32x2 %0, %1, %2;" : "=l"(d) : "l"(a), "l"(b)); return d;
}
__device__ __forceinline__ ull add2(ull a, ull b) {
    ull d; asm("add.rn.f32x2 %0, %1, %2;" : "=l"(d) : "l"(a), "l"(b)); return d;
}
__device__ __forceinline__ float lo2(ull a) {
    unsigned l, h; asm("mov.b64 {%0, %1}, %2;" : "=r"(l), "=r"(h) : "l"(a)); return __uint_as_float(l);
}
__device__ __forceinline__ float hi2(ull a) {
    unsigned l, h; asm("mov.b64 {%0, %1}, %2;" : "=r"(l), "=r"(h) : "l"(a)); return __uint_as_float(h);
}
__device__ __forceinline__ uint32_t smem_u32(const void* p) {
    uint32_t a; asm("{ .reg .u64 t; cvta.to.shared.u64 t, %1; cvt.u32.u64 %0, t; }" : "=r"(a) : "l"(p));
    return a;
}
__device__ __forceinline__ void cp16(uint32_t dst, const void* src) {
    asm volatile("cp.async.cg.shared.global [%0], [%1], 16;" :: "r"(dst), "l"(src) : "memory");
}
__device__ __forceinline__ void cp4(uint32_t dst, const void* src) {
    asm volatile("cp.async.ca.shared.global [%0], [%1], 4;" :: "r"(dst), "l"(src) : "memory");
}
#define CP_COMMIT() asm volatile("cp.async.commit_group;" ::: "memory")

#define MMA(D, A0, A1, A2, A3, B0, B1)                                          \
    asm volatile(                                                               \
        "mma.sync.aligned.m16n8k8.row.col.f32.tf32.tf32.f32 "                   \
        "{%0,%1,%2,%3}, {%4,%5,%6,%7}, {%8,%9}, {%0,%1,%2,%3};"                 \
        : "+f"((D)[0]), "+f"((D)[1]), "+f"((D)[2]), "+f"((D)[3])                \
        : "r"(A0), "r"(A1), "r"(A2), "r"(A3), "r"(B0), "r"(B1));

// ---------------------------------------------------------------------------
// Kernel 1: GEMM via mma.sync tf32 (round-10, unchanged / equal-best).
// ---------------------------------------------------------------------------
#define SA0   0
#define SA1   18432
#define SW0   36864
#define SW1   41984
#define SBIAS 47104
#define GSMEM 47232

__global__ __launch_bounds__(128) void gemm_kernel(const float* __restrict__ X,
                                                   const float* __restrict__ W,
                                                   const float* __restrict__ bias,
                                                   const int*   __restrict__ labels) {
    extern __shared__ char smem[];
    const uint32_t sb = smem_u32(smem);
    const int tid  = threadIdx.x;
    const int wid  = tid >> 5;
    const int lid  = tid & 31;
    const int grp  = lid >> 2;
    const int qd   = lid & 3;
    const int row0 = blockIdx.x * 128;

    if (blockIdx.x == 0 && tid == 0) g_cnt = 0;

    float* bias_s = (float*)(smem + SBIAS);
    if (tid < 32) bias_s[tid] = (tid < Ln) ? bias[tid] : 0.f;

    float c_[2][4][4];
#pragma unroll
    for (int mt = 0; mt < 2; ++mt)
#pragma unroll
        for (int nt = 0; nt < 4; ++nt)
#pragma unroll
            for (int r = 0; r < 4; ++r) c_[mt][nt][r] = 0.f;

#define STAGE(CK, BUF)                                                          \
    {                                                                           \
        uint32_t ab = sb + ((BUF) ? SA1 : SA0);                                 \
        uint32_t wb = sb + ((BUF) ? SW1 : SW0);                                 \
        _Pragma("unroll")                                                       \
        for (int t = 0; t < 8; ++t) {                                           \
            int i = t * 128 + tid;                                              \
            int r = i >> 3, q = i & 7;                                          \
            cp16(ab + (r * 36 + q * 4) * 4,                                     \
                 X + (size_t)(row0 + r) * Hn + (CK) * 32 + q * 4);              \
        }                                                                       \
        _Pragma("unroll")                                                       \
        for (int t = 0; t < 7; ++t) {                                           \
            int i = t * 128 + tid;                                              \
            if (i < 800) {                                                      \
                int k = i / 25, n = i - k * 25;                                 \
                cp4(wb + (k * 40 + n) * 4, W + (CK) * 800 + i);                 \
            }                                                                   \
        }                                                                       \
        CP_COMMIT();                                                            \
    }

    STAGE(0, 0)
    STAGE(1, 1)

    for (int ck = 0; ck < 24; ++ck) {
        if (ck < 23) asm volatile("cp.async.wait_group 1;" ::: "memory");
        else         asm volatile("cp.async.wait_group 0;" ::: "memory");
        __syncthreads();

        const int buf = ck & 1;
        const float* As = (const float*)(smem + (buf ? SA1 : SA0));
        const float* Ws = (const float*)(smem + (buf ? SW1 : SW0));

#pragma unroll
        for (int ks = 0; ks < 4; ++ks) {
            const int k0 = ks * 8;
            uint32_t a[2][4], b[4][2];
#pragma unroll
            for (int mt = 0; mt < 2; ++mt) {
                int r = wid * 32 + mt * 16 + grp;
                a[mt][0] = __float_as_uint(As[r * 36 + k0 + qd]);
                a[mt][1] = __float_as_uint(As[(r + 8) * 36 + k0 + qd]);
                a[mt][2] = __float_as_uint(As[r * 36 + k0 + qd + 4]);
                a[mt][3] = __float_as_uint(As[(r + 8) * 36 + k0 + qd + 4]);
            }
#pragma unroll
            for (int nt = 0; nt < 4; ++nt) {
                int n = nt * 8 + grp;
                float b0 = (n < Ln) ? Ws[(k0 + qd) * 40 + n] : 0.f;
                float b1 = (n < Ln) ? Ws[(k0 + qd + 4) * 40 + n] : 0.f;
                b[nt][0] = __float_as_uint(b0);
                b[nt][1] = __float_as_uint(b1);
            }
#pragma unroll
            for (int mt = 0; mt < 2; ++mt)
#pragma unroll
                for (int nt = 0; nt < 4; ++nt)
                    MMA(c_[mt][nt], a[mt][0], a[mt][1], a[mt][2], a[mt][3],
                        b[nt][0], b[nt][1])
        }
        __syncthreads();
        if (ck + 2 < 24) STAGE(ck + 2, buf)
    }

    float* pem = (float*)(smem + 0);
    float* pee = (float*)(smem + 12800);
#pragma unroll
    for (int mt = 0; mt < 2; ++mt) {
        int rb = wid * 32 + mt * 16 + grp;
#pragma unroll
        for (int nt = 0; nt < 4; ++nt) {
            int col = nt * 8 + 2 * qd;
            if (col < Ln) {
                float v0 = c_[mt][nt][0] + bias_s[col];
                float v2 = c_[mt][nt][2] + bias_s[col];
                pem[rb * Ln + col]       = v0;
                pem[(rb + 8) * Ln + col] = v2;
                pee[rb * Ln + col]       = __expf(v0);
                pee[(rb + 8) * Ln + col] = __expf(v2);
            }
            if (col + 1 < Ln) {
                float v1 = c_[mt][nt][1] + bias_s[col + 1];
                float v3 = c_[mt][nt][3] + bias_s[col + 1];
                pem[rb * Ln + col + 1]       = v1;
                pem[(rb + 8) * Ln + col + 1] = v3;
                pee[rb * Ln + col + 1]       = __expf(v1);
                pee[(rb + 8) * Ln + col + 1] = __expf(v3);
            }
        }
    }
    __syncthreads();
    {
        int lab = labels[row0 + tid];
        g_emtag[row0 + tid] = pem[tid * Ln + lab];
        const float4* s1 = (const float4*)pee;
        float4* g1 = (float4*)(g_eem + (size_t)row0 * Ln);
#pragma unroll
        for (int t = 0; t < 7; ++t) {
            int i = t * 128 + tid;
            if (i < 800) g1[i] = s1[i];
        }
    }
}

// ---------------------------------------------------------------------------
// Kernel 2: pair producer. H_s = G_{2s+1} * G_{2s+2}  (s<255), H_255 = G_511.
// One warp per (batch, pair). mma m16n8k8 tf32 on 32x32x32-padded matmul.
// Output Ht[b][s][j][28] = H[k][j] at [j*28+k], k=25..27 zeroed.
// ---------------------------------------------------------------------------
__global__ __launch_bounds__(128) void pair_kernel(const int* __restrict__ mask,
                                                   const float* __restrict__ trans) {
    __shared__ float Te[32 * 33];        // exp(trans), zero-padded
    __shared__ float Hsm[4][700];

    const int tid  = threadIdx.x;
    const int wid  = tid >> 5;
    const int lane = tid & 31;
    const int grp  = lane >> 2;
    const int qd   = lane & 3;

    for (int i = tid; i < 32 * 33; i += 128) Te[i] = 0.f;
    __syncthreads();
    for (int i = tid; i < 625; i += 128) {
        int k = i / 25, j = i - k * 25;
        Te[k * 33 + j] = __expf(trans[i]);
    }
    __syncthreads();

    const int b = blockIdx.x >> 6;                  // 64 batches
    const int s = ((blockIdx.x & 63) << 2) | wid;   // 256 pairs
    const int ta = 2 * s + 1;
    const int tb = 2 * s + 2;
    const int ma = mask[b * Tn + ta];
    const int mb = (s < 255) ? mask[b * Tn + tb] : 0;

    const float* ea_p = g_eem + ((size_t)b * Tn + ta) * Ln;
    const float* eb_p = g_eem + ((size_t)b * Tn + tb) * Ln;
    float* hs = Hsm[wid];
    float* Hout = g_H + ((size_t)b * 256 + s) * 700;

    for (int i = lane; i < 700; i += 32) hs[i] = 0.f;
    __syncwarp();

    if (ma && mb) {
        // constant Te fragments
        float teA[2][4][4];       // [mt][kt][u*2+v]
#pragma unroll
        for (int mt = 0; mt < 2; ++mt)
#pragma unroll
            for (int kt = 0; kt < 4; ++kt)
#pragma unroll
                for (int u = 0; u < 2; ++u)
#pragma unroll
                    for (int v = 0; v < 2; ++v)
                        teA[mt][kt][u * 2 + v] =
                            Te[(grp + 8 * u + 16 * mt) * 33 + (qd + 4 * v + 8 * kt)];
        uint32_t tb0[4][4], tb1[4][4];   // [nt][kt]
#pragma unroll
        for (int nt = 0; nt < 4; ++nt)
#pragma unroll
            for (int kt = 0; kt < 4; ++kt) {
                tb0[nt][kt] = __float_as_uint(Te[(qd + 8 * kt) * 33 + (grp + 8 * nt)]);
                tb1[nt][kt] = __float_as_uint(Te[(qd + 4 + 8 * kt) * 33 + (grp + 8 * nt)]);
            }
        // ea at this thread's k-columns
        float ea[4][2];
#pragma unroll
        for (int kt = 0; kt < 4; ++kt)
#pragma unroll
            for (int v = 0; v < 2; ++v) {
                int i = qd + 4 * v + 8 * kt;
                ea[kt][v] = (i < Ln) ? __ldg(ea_p + i) : 0.f;
            }

        float d[2][4][4];
#pragma unroll
        for (int mt = 0; mt < 2; ++mt)
#pragma unroll
            for (int nt = 0; nt < 4; ++nt)
#pragma unroll
                for (int r = 0; r < 4; ++r) d[mt][nt][r] = 0.f;

#pragma unroll
        for (int kt = 0; kt < 4; ++kt) {
            uint32_t a0[2], a1[2], a2[2], a3[2];
#pragma unroll
            for (int mt = 0; mt < 2; ++mt) {
                a0[mt] = __float_as_uint(teA[mt][kt][0] * ea[kt][0]);  // (grp,   qd)
                a1[mt] = __float_as_uint(teA[mt][kt][2] * ea[kt][0]);  // (grp+8, qd)
                a2[mt] = __float_as_uint(teA[mt][kt][1] * ea[kt][1]);  // (grp,   qd+4)
                a3[mt] = __float_as_uint(teA[mt][kt][3] * ea[kt][1]);  // (grp+8, qd+4)
            }
#pragma unroll
            for (int mt = 0; mt < 2; ++mt)
#pragma unroll
                for (int nt = 0; nt < 4; ++nt)
                    MMA(d[mt][nt], a0[mt], a1[mt], a2[mt], a3[mt],
                        tb0[nt][kt], tb1[nt][kt])
        }

        float eb[4][2];
#pragma unroll
        for (int nt = 0; nt < 4; ++nt)
#pragma unroll
            for (int z = 0; z < 2; ++z) {
                int c = 2 * qd + z + 8 * nt;
                eb[nt][z] = (c < Ln) ? __ldg(eb_p + c) : 0.f;
            }
#pragma unroll
        for (int mt = 0; mt < 2; ++mt)
#pragma unroll
            for (int nt = 0; nt < 4; ++nt) {
                int r0 = grp + 16 * mt, r1 = r0 + 8;
                int c0 = 2 * qd + 8 * nt, c1 = c0 + 1;
                if (c0 < Ln && r0 < Ln) hs[c0 * 28 + r0] = d[mt][nt][0] * eb[nt][0];
                if (c1 < Ln && r0 < Ln) hs[c1 * 28 + r0] = d[mt][nt][1] * eb[nt][1];
                if (c0 < Ln && r1 < Ln) hs[c0 * 28 + r1] = d[mt][nt][2] * eb[nt][0];
                if (c1 < Ln && r1 < Ln) hs[c1 * 28 + r1] = d[mt][nt][3] * eb[nt][1];
            }
    } else if (ma || mb) {
        // H = G_t : Ht[j][k] = Te[k][j] * eem_t[j]
        if (lane < Ln) {
            float e = __ldg((ma ? ea_p : eb_p) + lane);
#pragma unroll
            for (int k = 0; k < Ln; ++k)
                hs[lane * 28 + k] = Te[k * 33 + lane] * e;
        }
    } else {
        // identity
        if (lane < Ln) {
#pragma unroll
            for (int k = 0; k < Ln; ++k)
                hs[lane * 28 + k] = (k == lane) ? 1.f : 0.f;
        }
    }
    __syncwarp();
    {
        const float4* src = (const float4*)hs;
        float4* dst = (float4*)Hout;
        for (int i = lane; i < 175; i += 32) dst[i] = src[i];
    }
}

// ---------------------------------------------------------------------------
// Kernel 3: CRF consumer — 256 fused pair-steps. Mask & emission folded into
// H. cp.async double-buffered 8-pair chunks; renorm once per chunk.
// ---------------------------------------------------------------------------
#define LDH(H, ADDR)                                                            \
    asm volatile("ld.shared.v2.u64 {%0,%1}, [%2];"                              \
                 : "=l"((H)[0]), "=l"((H)[1]) : "r"(ADDR));                     \
    asm volatile("ld.shared.v2.u64 {%0,%1}, [%2];"                              \
                 : "=l"((H)[2]), "=l"((H)[3]) : "r"((ADDR) + 16));              \
    asm volatile("ld.shared.v2.u64 {%0,%1}, [%2];"                              \
                 : "=l"((H)[4]), "=l"((H)[5]) : "r"((ADDR) + 32));              \
    asm volatile("ld.shared.v2.u64 {%0,%1}, [%2];"                              \
                 : "=l"((H)[6]), "=l"((H)[7]) : "r"((ADDR) + 48));              \
    asm volatile("ld.shared.v2.u64 {%0,%1}, [%2];"                              \
                 : "=l"((H)[8]), "=l"((H)[9]) : "r"((ADDR) + 64));              \
    asm volatile("ld.shared.v2.u64 {%0,%1}, [%2];"                              \
                 : "=l"((H)[10]), "=l"((H)[11]) : "r"((ADDR) + 80));            \
    asm volatile("ld.shared.u64 %0, [%1];"                                      \
                 : "=l"((H)[12]) : "r"((ADDR) + 96));

#define CRF_PSTEP(HC)                                                           \
    {                                                                           \
        asm volatile("st.shared.b32 [%0], %1;"                                  \
                     :: "r"(pbase + 4u * (unsigned)j),                          \
                        "r"(__float_as_uint(p)) : "memory");                    \
        ull w0,w1,w2,w3,w4,w5,w6,w7,w8,w9,w10,w11,w12;                          \
        asm volatile("ld.shared.v2.u64 {%0,%1}, [%2];"                          \
                     : "=l"(w0), "=l"(w1) : "r"(pbase));                        \
        asm volatile("ld.shared.v2.u64 {%0,%1}, [%2];"                          \
                     : "=l"(w2), "=l"(w3) : "r"(pbase + 16));                   \
        asm volatile("ld.shared.v2.u64 {%0,%1}, [%2];"                          \
                     : "=l"(w4), "=l"(w5) : "r"(pbase + 32));                   \
        asm volatile("ld.shared.v2.u64 {%0,%1}, [%2];"                          \
                     : "=l"(w6), "=l"(w7) : "r"(pbase + 48));                   \
        asm volatile("ld.shared.v2.u64 {%0,%1}, [%2];"                          \
                     : "=l"(w8), "=l"(w9) : "r"(pbase + 64));                   \
        asm volatile("ld.shared.v2.u64 {%0,%1}, [%2];"                          \
                     : "=l"(w10), "=l"(w11) : "r"(pbase + 80));                 \
        asm volatile("ld.shared.u64 %0, [%1];"                                  \
                     : "=l"(w12) : "r"(pbase + 96));                            \
        ull A0 = mul2(w0, (HC)[0]);                                             \
        ull A1 = mul2(w1, (HC)[1]);                                             \
        ull A2 = mul2(w2, (HC)[2]);                                             \
        ull A3 = mul2(w3, (HC)[3]);                                             \
        ull A4 = mul2(w4, (HC)[4]);                                             \
        ull A5 = mul2(w5, (HC)[5]);                                             \
        ull A6 = mul2(w6, (HC)[6]);                                             \
        A0 = fma2(w7,  (HC)[7],  A0);                                           \
        A1 = fma2(w8,  (HC)[8],  A1);                                           \
        A2 = fma2(w9,  (HC)[9],  A2);                                           \
        A3 = fma2(w10, (HC)[10], A3);                                           \
        A4 = fma2(w11, (HC)[11], A4);                                           \
        A5 = fma2(w12, (HC)[12], A5);                                           \
        ull T0 = add2(A0, A1);                                                  \
        ull T1 = add2(A2, A3);                                                  \
        ull T2 = add2(A4, A5);                                                  \
        T0 = add2(T0, T1);                                                      \
        T2 = add2(T2, A6);                                                      \
        T0 = add2(T0, T2);                                                      \
        p = lo2(T0) + hi2(T0);                                                  \
    }

#define CRF_RENORM                                                              \
    {                                                                           \
        unsigned mx = __reduce_max_sync(0xffffffffu, __float_as_uint(p));       \
        int e = (int)(mx >> 23);                                                \
        float sc = __uint_as_float((unsigned)(253 - e) << 23);                  \
        p *= sc;                                                                \
        C += (float)(e - 126) * 0.6931471805599453f;                            \
    }

#define STAGE_H(CH, BUF)                                                        \
    {                                                                           \
        const float* srcp = gHb + (size_t)(CH) * 5600;                          \
        uint32_t dstb = (BUF) ? hb1 : hb0;                                      \
        for (int i = j; i < 1400; i += 32)                                      \
            cp16(dstb + 16u * (unsigned)i, srcp + 4 * i);                       \
        CP_COMMIT();                                                            \
    }

__global__ __launch_bounds__(32) void crf_kernel(const int* __restrict__ mask,
                                                 const int* __restrict__ labels,
                                                 const float* __restrict__ trans,
                                                 const float* __restrict__ start_t,
                                                 const float* __restrict__ end_t,
                                                 float* __restrict__ out) {
    const int b  = blockIdx.x;
    const int j  = threadIdx.x;
    const int jc = (j < Ln) ? j : (Ln - 1);
    const bool lane_ok = (j < Ln);

    const float* gHb    = g_H + (size_t)b * 256 * 700;
    const float* emtagb = g_emtag + b * Tn;
    const int*   lb     = labels + b * Tn;

    __shared__ __align__(16) float Hbuf[2][5600];
    __shared__ __align__(16) float pbuf[32];
    __shared__ int smask[Tn];
    const uint32_t pbase = smem_u32(pbuf);
    const uint32_t hb0   = smem_u32(Hbuf[0]);
    const uint32_t hb1   = smem_u32(Hbuf[1]);

    STAGE_H(0, 0)
    STAGE_H(1, 1)

    for (int t = j; t < Tn; t += 32) smask[t] = mask[b * Tn + t];

    // ---- numerator (overlaps cp.async fill) ----
    float numv = 0.f; int msum = 0;
    for (int t = j; t < Tn; t += 32) {
        int m = smask[t];
        msum += m;
        if (t == 0)  numv += start_t[lb[0]] + emtagb[0];
        else if (m)  numv += trans[lb[t - 1] * Ln + lb[t]] + emtagb[t];
    }
#pragma unroll
    for (int off = 16; off; off >>= 1) {
        numv += __shfl_xor_sync(0xffffffffu, numv, off);
        msum += __shfl_xor_sync(0xffffffffu, msum, off);
    }

    const float eend = __expf(end_t[jc]);

    // p0 = exp(start) * exp(em_0)
    float p = __expf(start_t[jc]) * __ldg(g_eem + (size_t)b * Tn * Ln + jc);
    float C = 0.f;

    for (int c = 0; c < 32; ++c) {
        if (c < 31) asm volatile("cp.async.wait_group 1;" ::: "memory");
        else        asm volatile("cp.async.wait_group 0;" ::: "memory");
        __syncwarp();
        const uint32_t hrow = ((c & 1) ? hb1 : hb0) + (unsigned)jc * 112;

        ull hcur[13], hnx[13];
        LDH(hcur, hrow)
#pragma unroll
        for (int u = 0; u < 8; ++u) {
            if (u < 7) { LDH(hnx, hrow + (unsigned)(u + 1) * 2800) }
            CRF_PSTEP(hcur)
            if (u < 7) {
#pragma unroll
                for (int q = 0; q < 13; ++q) hcur[q] = hnx[q];
            }
        }
        CRF_RENORM
        if (c + 2 < 32) STAGE_H(c + 2, c & 1)
    }

    float tot = lane_ok ? p * eend : 0.f;
#pragma unroll
    for (int off = 16; off; off >>= 1) tot += __shfl_xor_sync(0xffffffffu, tot, off);
    float denom = C + __logf(tot);

    if (j == 0) {
        int last = msum - 1;
        g_llh[b] = (numv + end_t[lb[last]]) - denom;
        __threadfence();
        int old = atomicAdd(&g_cnt, 1);
        if (old == Bn - 1) {
            __threadfence();
            float s = 0.f;
#pragma unroll 8
            for (int i = 0; i < Bn; ++i) s += __ldcv(&g_llh[i]);
            out[0] = -s * (1.0f / 64.0f);
        }
    }
}

// ---------------------------------------------------------------------------
extern "C" void kernel_launch(void* const* d_in, const int* in_sizes, int n_in,
                              void* d_out, int out_size) {
    const float* X      = (const float*)d_in[0];
    const int*   mask   = (const int*)  d_in[1];
    const int*   labels = (const int*)  d_in[2];
    const float* W      = (const float*)d_in[3];
    const float* bias   = (const float*)d_in[4];
    const float* trans  = (const float*)d_in[5];
    const float* st     = (const float*)d_in[6];
    const float* en     = (const float*)d_in[7];
    float* out = (float*)d_out;

    gemm_kernel<<<256, 128, GSMEM>>>(X, W, bias, labels);
    pair_kernel<<<4096, 128>>>(mask, trans);
    crf_kernel<<<Bn, 32>>>(mask, labels, trans, st, en, out);
}

// round 12
// speedup vs baseline: 1.1875x; 1.1875x over previous
#include <cuda_runtime.h>
#include <math.h>
#include <stdint.h>

#define Bn 64
#define Tn 512
#define Hn 768
#define Ln 25

__device__ __align__(16) float g_eem  [Bn * Tn * Ln];
__device__ __align__(16) float g_emtag[Bn * Tn];
__device__ float g_llh[Bn];
__device__ int   g_cnt;

typedef unsigned long long ull;

__device__ __forceinline__ ull fma2(ull a, ull b, ull c) {
    ull d; asm("fma.rn.f32x2 %0, %1, %2, %3;" : "=l"(d) : "l"(a), "l"(b), "l"(c)); return d;
}
__device__ __forceinline__ ull mul2(ull a, ull b) {
    ull d; asm("mul.rn.f32x2 %0, %1, %2;" : "=l"(d) : "l"(a), "l"(b)); return d;
}
__device__ __forceinline__ ull add2(ull a, ull b) {
    ull d; asm("add.rn.f32x2 %0, %1, %2;" : "=l"(d) : "l"(a), "l"(b)); return d;
}
__device__ __forceinline__ float lo2(ull a) {
    unsigned l, h; asm("mov.b64 {%0, %1}, %2;" : "=r"(l), "=r"(h) : "l"(a)); return __uint_as_float(l);
}
__device__ __forceinline__ float hi2(ull a) {
    unsigned l, h; asm("mov.b64 {%0, %1}, %2;" : "=r"(l), "=r"(h) : "l"(a)); return __uint_as_float(h);
}
__device__ __forceinline__ uint32_t smem_u32(const void* p) {
    uint32_t a; asm("{ .reg .u64 t; cvta.to.shared.u64 t, %1; cvt.u32.u64 %0, t; }" : "=r"(a) : "l"(p));
    return a;
}
__device__ __forceinline__ void cp16(uint32_t dst, const void* src) {
    asm volatile("cp.async.cg.shared.global [%0], [%1], 16;" :: "r"(dst), "l"(src) : "memory");
}
__device__ __forceinline__ void cp4(uint32_t dst, const void* src) {
    asm volatile("cp.async.ca.shared.global [%0], [%1], 4;" :: "r"(dst), "l"(src) : "memory");
}
#define CP_COMMIT() asm volatile("cp.async.commit_group;" ::: "memory")

#define MMA(D, A0, A1, A2, A3, B0, B1)                                          \
    asm volatile(                                                               \
        "mma.sync.aligned.m16n8k8.row.col.f32.tf32.tf32.f32 "                   \
        "{%0,%1,%2,%3}, {%4,%5,%6,%7}, {%8,%9}, {%0,%1,%2,%3};"                 \
        : "+f"((D)[0]), "+f"((D)[1]), "+f"((D)[2]), "+f"((D)[3])                \
        : "r"(A0), "r"(A1), "r"(A2), "r"(A3), "r"(B0), "r"(B1));

// ---------------------------------------------------------------------------
// Kernel 1: GEMM via mma.sync tf32 (round-10 best, unchanged).
// ---------------------------------------------------------------------------
#define SA0   0
#define SA1   18432
#define SW0   36864
#define SW1   41984
#define SBIAS 47104
#define GSMEM 47232

__global__ __launch_bounds__(128) void gemm_kernel(const float* __restrict__ X,
                                                   const float* __restrict__ W,
                                                   const float* __restrict__ bias,
                                                   const int*   __restrict__ labels) {
    extern __shared__ char smem[];
    const uint32_t sb = smem_u32(smem);
    const int tid  = threadIdx.x;
    const int wid  = tid >> 5;
    const int lid  = tid & 31;
    const int grp  = lid >> 2;
    const int qd   = lid & 3;
    const int row0 = blockIdx.x * 128;

    if (blockIdx.x == 0 && tid == 0) g_cnt = 0;

    float* bias_s = (float*)(smem + SBIAS);
    if (tid < 32) bias_s[tid] = (tid < Ln) ? bias[tid] : 0.f;

    float c_[2][4][4];
#pragma unroll
    for (int mt = 0; mt < 2; ++mt)
#pragma unroll
        for (int nt = 0; nt < 4; ++nt)
#pragma unroll
            for (int r = 0; r < 4; ++r) c_[mt][nt][r] = 0.f;

#define STAGE(CK, BUF)                                                          \
    {                                                                           \
        uint32_t ab = sb + ((BUF) ? SA1 : SA0);                                 \
        uint32_t wb = sb + ((BUF) ? SW1 : SW0);                                 \
        _Pragma("unroll")                                                       \
        for (int t = 0; t < 8; ++t) {                                           \
            int i = t * 128 + tid;                                              \
            int r = i >> 3, q = i & 7;                                          \
            cp16(ab + (r * 36 + q * 4) * 4,                                     \
                 X + (size_t)(row0 + r) * Hn + (CK) * 32 + q * 4);              \
        }                                                                       \
        _Pragma("unroll")                                                       \
        for (int t = 0; t < 7; ++t) {                                           \
            int i = t * 128 + tid;                                              \
            if (i < 800) {                                                      \
                int k = i / 25, n = i - k * 25;                                 \
                cp4(wb + (k * 40 + n) * 4, W + (CK) * 800 + i);                 \
            }                                                                   \
        }                                                                       \
        CP_COMMIT();                                                            \
    }

    STAGE(0, 0)
    STAGE(1, 1)

    for (int ck = 0; ck < 24; ++ck) {
        if (ck < 23) asm volatile("cp.async.wait_group 1;" ::: "memory");
        else         asm volatile("cp.async.wait_group 0;" ::: "memory");
        __syncthreads();

        const int buf = ck & 1;
        const float* As = (const float*)(smem + (buf ? SA1 : SA0));
        const float* Ws = (const float*)(smem + (buf ? SW1 : SW0));

#pragma unroll
        for (int ks = 0; ks < 4; ++ks) {
            const int k0 = ks * 8;
            uint32_t a[2][4], b[4][2];
#pragma unroll
            for (int mt = 0; mt < 2; ++mt) {
                int r = wid * 32 + mt * 16 + grp;
                a[mt][0] = __float_as_uint(As[r * 36 + k0 + qd]);
                a[mt][1] = __float_as_uint(As[(r + 8) * 36 + k0 + qd]);
                a[mt][2] = __float_as_uint(As[r * 36 + k0 + qd + 4]);
                a[mt][3] = __float_as_uint(As[(r + 8) * 36 + k0 + qd + 4]);
            }
#pragma unroll
            for (int nt = 0; nt < 4; ++nt) {
                int n = nt * 8 + grp;
                float b0 = (n < Ln) ? Ws[(k0 + qd) * 40 + n] : 0.f;
                float b1 = (n < Ln) ? Ws[(k0 + qd + 4) * 40 + n] : 0.f;
                b[nt][0] = __float_as_uint(b0);
                b[nt][1] = __float_as_uint(b1);
            }
#pragma unroll
            for (int mt = 0; mt < 2; ++mt)
#pragma unroll
                for (int nt = 0; nt < 4; ++nt)
                    MMA(c_[mt][nt], a[mt][0], a[mt][1], a[mt][2], a[mt][3],
                        b[nt][0], b[nt][1])
        }
        __syncthreads();
        if (ck + 2 < 24) STAGE(ck + 2, buf)
    }

    float* pem = (float*)(smem + 0);
    float* pee = (float*)(smem + 12800);
#pragma unroll
    for (int mt = 0; mt < 2; ++mt) {
        int rb = wid * 32 + mt * 16 + grp;
#pragma unroll
        for (int nt = 0; nt < 4; ++nt) {
            int col = nt * 8 + 2 * qd;
            if (col < Ln) {
                float v0 = c_[mt][nt][0] + bias_s[col];
                float v2 = c_[mt][nt][2] + bias_s[col];
                pem[rb * Ln + col]       = v0;
                pem[(rb + 8) * Ln + col] = v2;
                pee[rb * Ln + col]       = __expf(v0);
                pee[(rb + 8) * Ln + col] = __expf(v2);
            }
            if (col + 1 < Ln) {
                float v1 = c_[mt][nt][1] + bias_s[col + 1];
                float v3 = c_[mt][nt][3] + bias_s[col + 1];
                pem[rb * Ln + col + 1]       = v1;
                pem[(rb + 8) * Ln + col + 1] = v3;
                pee[rb * Ln + col + 1]       = __expf(v1);
                pee[(rb + 8) * Ln + col + 1] = __expf(v3);
            }
        }
    }
    __syncthreads();
    {
        int lab = labels[row0 + tid];
        g_emtag[row0 + tid] = pem[tid * Ln + lab];
        const float4* s1 = (const float4*)pee;
        float4* g1 = (float4*)(g_eem + (size_t)row0 * Ln);
#pragma unroll
        for (int t = 0; t < 7; ++t) {
            int i = t * 128 + tid;
            if (i < 800) g1[i] = s1[i];
        }
    }
}

// ---------------------------------------------------------------------------
// Kernel 2: fused CRF — per-batch block (256 thr). Phase 1: 8 warps build 64
// chunk matrices (8 steps each) in smem via mma; Phase 2: warp 0 scans 64
// steps. All H traffic stays in smem. Scale 2^-5 folded per applied G.
// ---------------------------------------------------------------------------
#define CHC    0            // Hc: 64 * 700 floats = 179200 B
#define CSCR   179200       // scratch: 8 warps * 32*36 floats = 36864 B
#define CTE    216064       // Te: 32*33 floats = 4224 B
#define CPB    220288       // pbuf: 128 B
#define CMSK   220416       // smask: 2048 B
#define CNUM   222464       // 16 B (numerator, msum)
#define CSMEM  222592

#define LN2F 0.6931471805599453f

#define LDH(H, ADDR)                                                            \
    asm volatile("ld.shared.v2.u64 {%0,%1}, [%2];"                              \
                 : "=l"((H)[0]), "=l"((H)[1]) : "r"(ADDR));                     \
    asm volatile("ld.shared.v2.u64 {%0,%1}, [%2];"                              \
                 : "=l"((H)[2]), "=l"((H)[3]) : "r"((ADDR) + 16));              \
    asm volatile("ld.shared.v2.u64 {%0,%1}, [%2];"                              \
                 : "=l"((H)[4]), "=l"((H)[5]) : "r"((ADDR) + 32));              \
    asm volatile("ld.shared.v2.u64 {%0,%1}, [%2];"                              \
                 : "=l"((H)[6]), "=l"((H)[7]) : "r"((ADDR) + 48));              \
    asm volatile("ld.shared.v2.u64 {%0,%1}, [%2];"                              \
                 : "=l"((H)[8]), "=l"((H)[9]) : "r"((ADDR) + 64));              \
    asm volatile("ld.shared.v2.u64 {%0,%1}, [%2];"                              \
                 : "=l"((H)[10]), "=l"((H)[11]) : "r"((ADDR) + 80));            \
    asm volatile("ld.shared.u64 %0, [%1];"                                      \
                 : "=l"((H)[12]) : "r"((ADDR) + 96));

#define CRF_PSTEP(HC)                                                           \
    {                                                                           \
        asm volatile("st.shared.b32 [%0], %1;"                                  \
                     :: "r"(pbase + 4u * (unsigned)j),                          \
                        "r"(__float_as_uint(p)) : "memory");                    \
        ull w0,w1,w2,w3,w4,w5,w6,w7,w8,w9,w10,w11,w12;                          \
        asm volatile("ld.shared.v2.u64 {%0,%1}, [%2];"                          \
                     : "=l"(w0), "=l"(w1) : "r"(pbase));                        \
        asm volatile("ld.shared.v2.u64 {%0,%1}, [%2];"                          \
                     : "=l"(w2), "=l"(w3) : "r"(pbase + 16));                   \
        asm volatile("ld.shared.v2.u64 {%0,%1}, [%2];"                          \
                     : "=l"(w4), "=l"(w5) : "r"(pbase + 32));                   \
        asm volatile("ld.shared.v2.u64 {%0,%1}, [%2];"                          \
                     : "=l"(w6), "=l"(w7) : "r"(pbase + 48));                   \
        asm volatile("ld.shared.v2.u64 {%0,%1}, [%2];"                          \
                     : "=l"(w8), "=l"(w9) : "r"(pbase + 64));                   \
        asm volatile("ld.shared.v2.u64 {%0,%1}, [%2];"                          \
                     : "=l"(w10), "=l"(w11) : "r"(pbase + 80));                 \
        asm volatile("ld.shared.u64 %0, [%1];"                                  \
                     : "=l"(w12) : "r"(pbase + 96));                            \
        ull A0 = mul2(w0, (HC)[0]);                                             \
        ull A1 = mul2(w1, (HC)[1]);                                             \
        ull A2 = mul2(w2, (HC)[2]);                                             \
        ull A3 = mul2(w3, (HC)[3]);                                             \
        ull A4 = mul2(w4, (HC)[4]);                                             \
        ull A5 = mul2(w5, (HC)[5]);                                             \
        ull A6 = mul2(w6, (HC)[6]);                                             \
        A0 = fma2(w7,  (HC)[7],  A0);                                           \
        A1 = fma2(w8,  (HC)[8],  A1);                                           \
        A2 = fma2(w9,  (HC)[9],  A2);                                           \
        A3 = fma2(w10, (HC)[10], A3);                                           \
        A4 = fma2(w11, (HC)[11], A4);                                           \
        A5 = fma2(w12, (HC)[12], A5);                                           \
        ull T0 = add2(A0, A1);                                                  \
        ull T1 = add2(A2, A3);                                                  \
        ull T2 = add2(A4, A5);                                                  \
        T0 = add2(T0, T1);                                                      \
        T2 = add2(T2, A6);                                                      \
        T0 = add2(T0, T2);                                                      \
        p = lo2(T0) + hi2(T0);                                                  \
    }

#define CRF_RENORM                                                              \
    {                                                                           \
        unsigned mx = __reduce_max_sync(0xffffffffu, __float_as_uint(p));       \
        int e = (int)(mx >> 23);                                                \
        float sc = __uint_as_float((unsigned)(253 - e) << 23);                  \
        p *= sc;                                                                \
        C += (float)(e - 126) * LN2F;                                           \
    }

__global__ __launch_bounds__(256) void crf_kernel(const int* __restrict__ mask,
                                                  const int* __restrict__ labels,
                                                  const float* __restrict__ trans,
                                                  const float* __restrict__ start_t,
                                                  const float* __restrict__ end_t,
                                                  float* __restrict__ out) {
    extern __shared__ char cs[];
    float* Hc     = (float*)(cs + CHC);
    float* Te     = (float*)(cs + CTE);
    float* pbuf   = (float*)(cs + CPB);
    int*   smaskp = (int*)  (cs + CMSK);
    float* numsh  = (float*)(cs + CNUM);

    const int b    = blockIdx.x;
    const int tid  = threadIdx.x;
    const int wid  = tid >> 5;
    const int lane = tid & 31;
    const int grp  = lane >> 2;
    const int qd   = lane & 3;
    const float S  = 0.03125f;   // 2^-5 per applied G

    const float* eemB   = g_eem + (size_t)b * Tn * Ln;
    const float* emtagb = g_emtag + b * Tn;
    const int*   lb     = labels + b * Tn;

    // ---- phase 0: smask + scaled exp(trans) table ----
    for (int t = tid; t < Tn; t += 256) smaskp[t] = mask[b * Tn + t];
    for (int i = tid; i < 32 * 33; i += 256) Te[i] = 0.f;
    __syncthreads();
    for (int i = tid; i < 625; i += 256) {
        int k = i / 25, jj = i - k * 25;
        Te[k * 33 + jj] = __expf(trans[i]) * S;
    }
    __syncthreads();

    // ---- phase 1: warp 7 numerator; all warps chunk products ----
    if (wid == 7) {
        float numv = 0.f; int msum = 0;
        for (int t = lane; t < Tn; t += 32) {
            int m = smaskp[t];
            msum += m;
            if (t == 0)  numv += start_t[lb[0]] + emtagb[0];
            else if (m)  numv += trans[lb[t - 1] * Ln + lb[t]] + emtagb[t];
        }
#pragma unroll
        for (int off = 16; off; off >>= 1) {
            numv += __shfl_xor_sync(0xffffffffu, numv, off);
            msum += __shfl_xor_sync(0xffffffffu, msum, off);
        }
        if (lane == 0) {
            numsh[0] = numv + end_t[lb[msum - 1]];
            numsh[1] = (float)msum;
        }
    }

    // per-warp constant B fragments of scaled Te
    float tb0f[4][4], tb1f[4][4];
#pragma unroll
    for (int nt = 0; nt < 4; ++nt)
#pragma unroll
        for (int kt = 0; kt < 4; ++kt) {
            tb0f[nt][kt] = Te[(qd + 8 * kt) * 33 + (grp + 8 * nt)];
            tb1f[nt][kt] = Te[(qd + 4 + 8 * kt) * 33 + (grp + 8 * nt)];
        }

    float* scr = (float*)(cs + CSCR) + wid * 32 * 36;

    for (int c = wid; c < 64; c += 8) {
        const int t0 = 1 + c * 8;
        uint32_t afr[2][4][4];
        float dreg[2][4][4];
        int napp = 0;
        bool pend = false;

#pragma unroll 1
        for (int u = 0; u < 8; ++u) {
            int t = t0 + u;
            if (t > 511) break;
            if (!smaskp[t]) continue;
            const float* ee = eemB + (size_t)t * Ln;

            if (napp == 0) {
                // P = G_t directly into A fragments
#pragma unroll
                for (int kt = 0; kt < 4; ++kt) {
                    int c0 = qd + 8 * kt, c1 = qd + 4 + 8 * kt;
                    float ea0 = (c0 < Ln) ? __ldg(ee + c0) : 0.f;
                    float ea1 = (c1 < Ln) ? __ldg(ee + c1) : 0.f;
#pragma unroll
                    for (int mt = 0; mt < 2; ++mt) {
                        int r0 = grp + 16 * mt;
                        afr[mt][kt][0] = __float_as_uint(Te[r0 * 33 + c0] * ea0);
                        afr[mt][kt][1] = __float_as_uint(Te[(r0 + 8) * 33 + c0] * ea0);
                        afr[mt][kt][2] = __float_as_uint(Te[r0 * 33 + c1] * ea1);
                        afr[mt][kt][3] = __float_as_uint(Te[(r0 + 8) * 33 + c1] * ea1);
                    }
                }
                napp = 1;
            } else {
                if (pend) {
                    // reorg D -> A via scratch
#pragma unroll
                    for (int mt = 0; mt < 2; ++mt)
#pragma unroll
                        for (int nt = 0; nt < 4; ++nt) {
                            int r0 = grp + 16 * mt, cc = 8 * nt + 2 * qd;
                            scr[r0 * 36 + cc]           = dreg[mt][nt][0];
                            scr[r0 * 36 + cc + 1]       = dreg[mt][nt][1];
                            scr[(r0 + 8) * 36 + cc]     = dreg[mt][nt][2];
                            scr[(r0 + 8) * 36 + cc + 1] = dreg[mt][nt][3];
                        }
                    __syncwarp();
#pragma unroll
                    for (int mt = 0; mt < 2; ++mt)
#pragma unroll
                        for (int kt = 0; kt < 4; ++kt) {
                            int r0 = grp + 16 * mt, c0 = qd + 8 * kt;
                            afr[mt][kt][0] = __float_as_uint(scr[r0 * 36 + c0]);
                            afr[mt][kt][1] = __float_as_uint(scr[(r0 + 8) * 36 + c0]);
                            afr[mt][kt][2] = __float_as_uint(scr[r0 * 36 + c0 + 4]);
                            afr[mt][kt][3] = __float_as_uint(scr[(r0 + 8) * 36 + c0 + 4]);
                        }
                    __syncwarp();
                }
                // eem columns for B (n = grp + 8nt)
                float eb[4];
#pragma unroll
                for (int nt = 0; nt < 4; ++nt) {
                    int n = grp + 8 * nt;
                    eb[nt] = (n < Ln) ? __ldg(ee + n) : 0.f;
                }
#pragma unroll
                for (int mt = 0; mt < 2; ++mt)
#pragma unroll
                    for (int nt = 0; nt < 4; ++nt)
#pragma unroll
                        for (int r = 0; r < 4; ++r) dreg[mt][nt][r] = 0.f;
#pragma unroll
                for (int kt = 0; kt < 4; ++kt) {
                    uint32_t bb0[4], bb1[4];
#pragma unroll
                    for (int nt = 0; nt < 4; ++nt) {
                        bb0[nt] = __float_as_uint(tb0f[nt][kt] * eb[nt]);
                        bb1[nt] = __float_as_uint(tb1f[nt][kt] * eb[nt]);
                    }
#pragma unroll
                    for (int mt = 0; mt < 2; ++mt)
#pragma unroll
                        for (int nt = 0; nt < 4; ++nt)
                            MMA(dreg[mt][nt], afr[mt][kt][0], afr[mt][kt][1],
                                afr[mt][kt][2], afr[mt][kt][3], bb0[nt], bb1[nt])
                }
                pend = true;
                ++napp;
            }
        }

        // write chunk matrix: Hc[c][j*28 + a] = P[a][j]
        float* hs = Hc + c * 700;
        if (napp == 0) {
            if (lane < Ln)
#pragma unroll
                for (int k = 0; k < 28; ++k) hs[lane * 28 + k] = (k == lane) ? 1.f : 0.f;
        } else if (napp == 1) {
#pragma unroll
            for (int mt = 0; mt < 2; ++mt)
#pragma unroll
                for (int kt = 0; kt < 4; ++kt) {
                    int r0 = grp + 16 * mt, r1 = r0 + 8;
                    int c0 = qd + 8 * kt,   c1 = c0 + 4;
                    if (c0 < Ln && r0 < 28) hs[c0 * 28 + r0] = __uint_as_float(afr[mt][kt][0]);
                    if (c0 < Ln && r1 < 28) hs[c0 * 28 + r1] = __uint_as_float(afr[mt][kt][1]);
                    if (c1 < Ln && r0 < 28) hs[c1 * 28 + r0] = __uint_as_float(afr[mt][kt][2]);
                    if (c1 < Ln && r1 < 28) hs[c1 * 28 + r1] = __uint_as_float(afr[mt][kt][3]);
                }
        } else {
#pragma unroll
            for (int mt = 0; mt < 2; ++mt)
#pragma unroll
                for (int nt = 0; nt < 4; ++nt) {
                    int r0 = grp + 16 * mt, r1 = r0 + 8;
                    int c0 = 8 * nt + 2 * qd, c1 = c0 + 1;
                    if (c0 < Ln && r0 < 28) hs[c0 * 28 + r0] = dreg[mt][nt][0];
                    if (c1 < Ln && r0 < 28) hs[c1 * 28 + r0] = dreg[mt][nt][1];
                    if (c0 < Ln && r1 < 28) hs[c0 * 28 + r1] = dreg[mt][nt][2];
                    if (c1 < Ln && r1 < 28) hs[c1 * 28 + r1] = dreg[mt][nt][3];
                }
        }
    }
    __syncthreads();

    // ---- phase 2: warp 0 scans the 64 chunk matrices ----
    if (wid != 0) return;

    const int j  = lane;
    const int jc = (j < Ln) ? j : (Ln - 1);
    const bool lane_ok = (j < Ln);
    const uint32_t pbase  = smem_u32(pbuf);
    const uint32_t hcbase = smem_u32(Hc);

    const float eend = __expf(end_t[jc]);
    float p = __expf(start_t[jc]) * __ldg(eemB + jc);
    float C = 0.f;

    ull hc[13], hn[13];
    LDH(hc, hcbase + (unsigned)jc * 112)
#pragma unroll 4
    for (int c = 0; c < 64; ++c) {
        if (c < 63) { LDH(hn, hcbase + (unsigned)(c + 1) * 2800 + (unsigned)jc * 112) }
        CRF_PSTEP(hc)
        CRF_RENORM
        if (c < 63) {
#pragma unroll
            for (int q = 0; q < 13; ++q) hc[q] = hn[q];
        }
    }

    float tot = lane_ok ? p * eend : 0.f;
#pragma unroll
    for (int off = 16; off; off >>= 1) tot += __shfl_xor_sync(0xffffffffu, tot, off);

    if (j == 0) {
        int   msum  = (int)numsh[1];
        int   n_act = msum - smaskp[0];           // active steps t>=1
        float denom = C + __logf(tot) + 5.0f * LN2F * (float)n_act;
        g_llh[b] = numsh[0] - denom;
        __threadfence();
        int old = atomicAdd(&g_cnt, 1);
        if (old == Bn - 1) {
            __threadfence();
            float s = 0.f;
#pragma unroll 8
            for (int i = 0; i < Bn; ++i) s += __ldcv(&g_llh[i]);
            out[0] = -s * (1.0f / 64.0f);
        }
    }
}

// ---------------------------------------------------------------------------
extern "C" void kernel_launch(void* const* d_in, const int* in_sizes, int n_in,
                              void* d_out, int out_size) {
    const float* X      = (const float*)d_in[0];
    const int*   mask   = (const int*)  d_in[1];
    const int*   labels = (const int*)  d_in[2];
    const float* W      = (const float*)d_in[3];
    const float* bias   = (const float*)d_in[4];
    const float* trans  = (const float*)d_in[5];
    const float* st     = (const float*)d_in[6];
    const float* en     = (const float*)d_in[7];
    float* out = (float*)d_out;

    cudaFuncSetAttribute(crf_kernel,
                         cudaFuncAttributeMaxDynamicSharedMemorySize, CSMEM);

    gemm_kernel<<<256, 128, GSMEM>>>(X, W, bias, labels);
    crf_kernel<<<Bn, 256, CSMEM>>>(mask, labels, trans, st, en, out);
}

// round 13
// speedup vs baseline: 1.8894x; 1.5910x over previous
#include <cuda_runtime.h>
#include <math.h>
#include <stdint.h>

#define Bn 64
#define Tn 512
#define Hn 768
#define Ln 25

__device__ __align__(16) float g_eem  [Bn * Tn * Ln];
__device__ __align__(16) float g_emtag[Bn * Tn];
__device__ float g_llh[Bn];
__device__ int   g_cnt;

typedef unsigned long long ull;

__device__ __forceinline__ ull fma2(ull a, ull b, ull c) {
    ull d; asm("fma.rn.f32x2 %0, %1, %2, %3;" : "=l"(d) : "l"(a), "l"(b), "l"(c)); return d;
}
__device__ __forceinline__ ull mul2(ull a, ull b) {
    ull d; asm("mul.rn.f32x2 %0, %1, %2;" : "=l"(d) : "l"(a), "l"(b)); return d;
}
__device__ __forceinline__ ull add2(ull a, ull b) {
    ull d; asm("add.rn.f32x2 %0, %1, %2;" : "=l"(d) : "l"(a), "l"(b)); return d;
}
__device__ __forceinline__ float lo2(ull a) {
    unsigned l, h; asm("mov.b64 {%0, %1}, %2;" : "=r"(l), "=r"(h) : "l"(a)); return __uint_as_float(l);
}
__device__ __forceinline__ float hi2(ull a) {
    unsigned l, h; asm("mov.b64 {%0, %1}, %2;" : "=r"(l), "=r"(h) : "l"(a)); return __uint_as_float(h);
}
__device__ __forceinline__ ull pack2(float l, float h) {
    ull d; asm("mov.b64 %0, {%1, %2};" : "=l"(d) : "r"(__float_as_uint(l)), "r"(__float_as_uint(h))); return d;
}
__device__ __forceinline__ uint32_t smem_u32(const void* p) {
    uint32_t a; asm("{ .reg .u64 t; cvta.to.shared.u64 t, %1; cvt.u32.u64 %0, t; }" : "=r"(a) : "l"(p));
    return a;
}
__device__ __forceinline__ void cp16(uint32_t dst, const void* src) {
    asm volatile("cp.async.cg.shared.global [%0], [%1], 16;" :: "r"(dst), "l"(src) : "memory");
}
__device__ __forceinline__ void cp4(uint32_t dst, const void* src) {
    asm volatile("cp.async.ca.shared.global [%0], [%1], 4;" :: "r"(dst), "l"(src) : "memory");
}
#define CP_COMMIT() asm volatile("cp.async.commit_group;" ::: "memory")

#define MMA(D, A0, A1, A2, A3, B0, B1)                                          \
    asm volatile(                                                               \
        "mma.sync.aligned.m16n8k8.row.col.f32.tf32.tf32.f32 "                   \
        "{%0,%1,%2,%3}, {%4,%5,%6,%7}, {%8,%9}, {%0,%1,%2,%3};"                 \
        : "+f"((D)[0]), "+f"((D)[1]), "+f"((D)[2]), "+f"((D)[3])                \
        : "r"(A0), "r"(A1), "r"(A2), "r"(A3), "r"(B0), "r"(B1));

// ---------------------------------------------------------------------------
// Kernel 1: GEMM via mma.sync tf32 — 512 blocks x 64 rows (occupancy 2x).
// ---------------------------------------------------------------------------
#define SA0   0
#define SA1   9216
#define SW0   18432
#define SW1   23552
#define SBIAS 28672
#define GSMEM 28800

__global__ __launch_bounds__(128) void gemm_kernel(const float* __restrict__ X,
                                                   const float* __restrict__ W,
                                                   const float* __restrict__ bias,
                                                   const int*   __restrict__ labels) {
    extern __shared__ char smem[];
    const uint32_t sb = smem_u32(smem);
    const int tid  = threadIdx.x;
    const int wid  = tid >> 5;
    const int lid  = tid & 31;
    const int grp  = lid >> 2;
    const int qd   = lid & 3;
    const int row0 = blockIdx.x * 64;

    if (blockIdx.x == 0 && tid == 0) g_cnt = 0;

    float* bias_s = (float*)(smem + SBIAS);
    if (tid < 32) bias_s[tid] = (tid < Ln) ? bias[tid] : 0.f;

    float c_[4][4];
#pragma unroll
    for (int nt = 0; nt < 4; ++nt)
#pragma unroll
        for (int r = 0; r < 4; ++r) c_[nt][r] = 0.f;

#define STAGE(CK, BUF)                                                          \
    {                                                                           \
        uint32_t ab = sb + ((BUF) ? SA1 : SA0);                                 \
        uint32_t wb = sb + ((BUF) ? SW1 : SW0);                                 \
        _Pragma("unroll")                                                       \
        for (int t = 0; t < 4; ++t) {                                           \
            int i = t * 128 + tid;                                              \
            int r = i >> 3, q = i & 7;                                          \
            cp16(ab + (r * 36 + q * 4) * 4,                                     \
                 X + (size_t)(row0 + r) * Hn + (CK) * 32 + q * 4);              \
        }                                                                       \
        _Pragma("unroll")                                                       \
        for (int t = 0; t < 7; ++t) {                                           \
            int i = t * 128 + tid;                                              \
            if (i < 800) {                                                      \
                int k = i / 25, n = i - k * 25;                                 \
                cp4(wb + (k * 40 + n) * 4, W + (CK) * 800 + i);                 \
            }                                                                   \
        }                                                                       \
        CP_COMMIT();                                                            \
    }

    STAGE(0, 0)
    STAGE(1, 1)

    for (int ck = 0; ck < 24; ++ck) {
        if (ck < 23) asm volatile("cp.async.wait_group 1;" ::: "memory");
        else         asm volatile("cp.async.wait_group 0;" ::: "memory");
        __syncthreads();

        const int buf = ck & 1;
        const float* As = (const float*)(smem + (buf ? SA1 : SA0));
        const float* Ws = (const float*)(smem + (buf ? SW1 : SW0));

#pragma unroll
        for (int ks = 0; ks < 4; ++ks) {
            const int k0 = ks * 8;
            uint32_t a0, a1, a2, a3, b[4][2];
            int r = wid * 16 + grp;
            a0 = __float_as_uint(As[r * 36 + k0 + qd]);
            a1 = __float_as_uint(As[(r + 8) * 36 + k0 + qd]);
            a2 = __float_as_uint(As[r * 36 + k0 + qd + 4]);
            a3 = __float_as_uint(As[(r + 8) * 36 + k0 + qd + 4]);
#pragma unroll
            for (int nt = 0; nt < 4; ++nt) {
                int n = nt * 8 + grp;
                float b0 = (n < Ln) ? Ws[(k0 + qd) * 40 + n] : 0.f;
                float b1 = (n < Ln) ? Ws[(k0 + qd + 4) * 40 + n] : 0.f;
                b[nt][0] = __float_as_uint(b0);
                b[nt][1] = __float_as_uint(b1);
            }
#pragma unroll
            for (int nt = 0; nt < 4; ++nt)
                MMA(c_[nt], a0, a1, a2, a3, b[nt][0], b[nt][1])
        }
        __syncthreads();
        if (ck + 2 < 24) STAGE(ck + 2, buf)
    }

    // ---- epilogue: pack em + exp(em) to smem; write eem + emtag ----
    float* pem = (float*)(smem + 0);
    float* pee = (float*)(smem + 6400);
    {
        int rb = wid * 16 + grp;
#pragma unroll
        for (int nt = 0; nt < 4; ++nt) {
            int col = nt * 8 + 2 * qd;
            if (col < Ln) {
                float v0 = c_[nt][0] + bias_s[col];
                float v2 = c_[nt][2] + bias_s[col];
                pem[rb * Ln + col]       = v0;
                pem[(rb + 8) * Ln + col] = v2;
                pee[rb * Ln + col]       = __expf(v0);
                pee[(rb + 8) * Ln + col] = __expf(v2);
            }
            if (col + 1 < Ln) {
                float v1 = c_[nt][1] + bias_s[col + 1];
                float v3 = c_[nt][3] + bias_s[col + 1];
                pem[rb * Ln + col + 1]       = v1;
                pem[(rb + 8) * Ln + col + 1] = v3;
                pee[rb * Ln + col + 1]       = __expf(v1);
                pee[(rb + 8) * Ln + col + 1] = __expf(v3);
            }
        }
    }
    __syncthreads();
    {
        if (tid < 64) {
            int lab = labels[row0 + tid];
            g_emtag[row0 + tid] = pem[tid * Ln + lab];
        }
        const float4* s1 = (const float4*)pee;
        float4* g1 = (float4*)(g_eem + (size_t)row0 * Ln);
#pragma unroll
        for (int t = 0; t < 4; ++t) {
            int i = t * 128 + tid;
            if (i < 400) g1[i] = s1[i];
        }
    }
}

// ---------------------------------------------------------------------------
// Kernel 2: bidirectional CRF. Warp0: forward t=1..255. Warp1: backward
// v <- G_t v for t=511..256 from v=exp(end). Warp2: numerator. Combine:
// Z = p . v ; fused last-finisher reduce.
// ---------------------------------------------------------------------------
#define LN2F 0.6931471805599453f

#define LDW13(PB)                                                               \
        ull w0,w1,w2,w3,w4,w5,w6,w7,w8,w9,w10,w11,w12;                          \
        asm volatile("ld.shared.v2.u64 {%0,%1}, [%2];"                          \
                     : "=l"(w0), "=l"(w1) : "r"(PB));                           \
        asm volatile("ld.shared.v2.u64 {%0,%1}, [%2];"                          \
                     : "=l"(w2), "=l"(w3) : "r"((PB) + 16));                    \
        asm volatile("ld.shared.v2.u64 {%0,%1}, [%2];"                          \
                     : "=l"(w4), "=l"(w5) : "r"((PB) + 32));                    \
        asm volatile("ld.shared.v2.u64 {%0,%1}, [%2];"                          \
                     : "=l"(w6), "=l"(w7) : "r"((PB) + 48));                    \
        asm volatile("ld.shared.v2.u64 {%0,%1}, [%2];"                          \
                     : "=l"(w8), "=l"(w9) : "r"((PB) + 64));                    \
        asm volatile("ld.shared.v2.u64 {%0,%1}, [%2];"                          \
                     : "=l"(w10), "=l"(w11) : "r"((PB) + 80));                  \
        asm volatile("ld.shared.u64 %0, [%1];"                                  \
                     : "=l"(w12) : "r"((PB) + 96));

#define DOT13(ET)                                                               \
        ull A0 = mul2(w0, (ET)[0]);                                             \
        ull A1 = mul2(w1, (ET)[1]);                                             \
        ull A2 = mul2(w2, (ET)[2]);                                             \
        ull A3 = mul2(w3, (ET)[3]);                                             \
        ull A4 = mul2(w4, (ET)[4]);                                             \
        ull A5 = mul2(w5, (ET)[5]);                                             \
        ull A6 = mul2(w6, (ET)[6]);                                             \
        A0 = fma2(w7,  (ET)[7],  A0);                                           \
        A1 = fma2(w8,  (ET)[8],  A1);                                           \
        A2 = fma2(w9,  (ET)[9],  A2);                                           \
        A3 = fma2(w10, (ET)[10], A3);                                           \
        A4 = fma2(w11, (ET)[11], A4);                                           \
        A5 = fma2(w12, (ET)[12], A5);                                           \
        ull T0 = add2(A0, A1);                                                  \
        ull T1 = add2(A2, A3);                                                  \
        ull T2 = add2(A4, A5);                                                  \
        T0 = add2(T0, T1);                                                      \
        T2 = add2(T2, A6);                                                      \
        T0 = add2(T0, T2);

// forward: store p, dot with column-constants, multiply by prefetched emission
#define CRF_FSTEP(TL, TG)                                                       \
    {                                                                           \
        float emn = ((TL) + 1 < 64) ? emsb[((TL) + 1) * Ln + jc] : 0.f;         \
        asm volatile("st.shared.b32 [%0], %1;"                                  \
                     :: "r"(pbase + 4u * (unsigned)j),                          \
                        "r"(__float_as_uint(p)) : "memory");                    \
        LDW13(pbase)                                                            \
        DOT13(et2)                                                              \
        float pn = (lo2(T0) + hi2(T0)) * emc;                                   \
        unsigned mb = (mwords[(TG) >> 5] >> ((TG) & 31)) & 1u;                  \
        p = mb ? pn : p;                                                        \
        emc = emn;                                                              \
    }

// backward: multiply by emission first (w = p*emc, lanes>=25 zero via emc),
// store, dot with row-constants
#define CRF_BSTEP(TL, TG)                                                       \
    {                                                                           \
        float emn = ((TL) > 0) ? emsb[((TL) - 1) * Ln + jc] * lane_okf : 0.f;   \
        float w   = p * emc;                                                    \
        asm volatile("st.shared.b32 [%0], %1;"                                  \
                     :: "r"(pbase + 4u * (unsigned)j),                          \
                        "r"(__float_as_uint(w)) : "memory");                    \
        LDW13(pbase)                                                            \
        DOT13(et2)                                                              \
        float pn = lo2(T0) + hi2(T0);                                           \
        unsigned mb = (mwords[(TG) >> 5] >> ((TG) & 31)) & 1u;                  \
        p = mb ? pn : p;                                                        \
        emc = emn;                                                              \
    }

#define CRF_RENORM                                                              \
    {                                                                           \
        unsigned mx = __reduce_max_sync(0xffffffffu, __float_as_uint(p));       \
        int e = (int)(mx >> 23);                                                \
        float sc = __uint_as_float((unsigned)(253 - e) << 23);                  \
        p *= sc;                                                                \
        C += (float)(e - 126) * LN2F;                                           \
    }

#define STAGE_EMS(C, DSTB)                                                      \
    {                                                                           \
        const float* srcp = eemB + (C) * 1600;                                  \
        for (int i = j; i < 400; i += 32)                                       \
            cp16((DSTB) + 16u * (unsigned)i, srcp + 4 * i);                     \
        CP_COMMIT();                                                            \
    }

__global__ __launch_bounds__(96) void crf_kernel(const int* __restrict__ mask,
                                                 const int* __restrict__ labels,
                                                 const float* __restrict__ trans,
                                                 const float* __restrict__ start_t,
                                                 const float* __restrict__ end_t,
                                                 float* __restrict__ out) {
    __shared__ __align__(16) float ems4[4][1600];
    __shared__ __align__(16) float pbufs[2][32];
    __shared__ __align__(16) float cmb[64];
    __shared__ float cmbC[2];
    __shared__ float numsh[2];
    __shared__ int   smaskp[Tn];

    const int b    = blockIdx.x;
    const int tid  = threadIdx.x;
    const int wid  = tid >> 5;
    const int j    = tid & 31;
    const int jc   = (j < Ln) ? j : (Ln - 1);
    const bool lane_ok  = (j < Ln);
    const float lane_okf = lane_ok ? 1.f : 0.f;

    const float* eemB   = g_eem + (size_t)b * Tn * Ln;
    const float* emtagb = g_emtag + b * Tn;
    const int*   lb     = labels + b * Tn;

    for (int t = tid; t < Tn; t += 96) smaskp[t] = mask[b * Tn + t];
    __syncthreads();

    if (wid == 0) {
        // ================= forward scan: t = 1..255 =================
        const uint32_t pbase = smem_u32(pbufs[0]);
        const uint32_t fb0 = smem_u32(ems4[0]);
        const uint32_t fb1 = smem_u32(ems4[1]);
        STAGE_EMS(0, fb0)
        STAGE_EMS(1, fb1)

        unsigned mwords[16];
#pragma unroll
        for (int w = 0; w < 16; ++w)
            mwords[w] = __ballot_sync(0xffffffffu, smaskp[w * 32 + j]);

        ull et2[13];
#pragma unroll
        for (int i = 0; i < 13; ++i) {
            float lo = __expf(trans[(2 * i) * Ln + jc]);
            float hi = (2 * i + 1 < Ln) ? __expf(trans[(2 * i + 1) * Ln + jc]) : 0.f;
            et2[i] = pack2(lo, hi);
        }

        float p = 0.f, C = 0.f;
        for (int c = 0; c < 4; ++c) {
            if (c < 3) asm volatile("cp.async.wait_group 1;" ::: "memory");
            else       asm volatile("cp.async.wait_group 0;" ::: "memory");
            __syncwarp();
            const float* emsb = ems4[c & 1];
            const int tbase = c * 64;

            if (c == 0) {
                p = __expf(start_t[jc]) * emsb[jc];
                float emc = emsb[Ln + jc];
#pragma unroll
                for (int u = 1; u < 16; ++u) CRF_FSTEP(u, u)
                CRF_RENORM
#pragma unroll
                for (int g = 1; g < 4; ++g) {
#pragma unroll
                    for (int u = 0; u < 16; ++u) CRF_FSTEP(g * 16 + u, g * 16 + u)
                    CRF_RENORM
                }
            } else {
                float emc = emsb[jc];
#pragma unroll
                for (int g = 0; g < 4; ++g) {
#pragma unroll
                    for (int u = 0; u < 16; ++u) CRF_FSTEP(g * 16 + u, tbase + g * 16 + u)
                    CRF_RENORM
                }
            }
            if (c + 2 < 4) STAGE_EMS(c + 2, (c & 1) ? fb1 : fb0)
        }
        cmb[j] = p;
        if (j == 0) cmbC[0] = C;
    } else if (wid == 1) {
        // ================= backward scan: t = 511..256 =================
        const uint32_t pbase = smem_u32(pbufs[1]);
        const uint32_t bb0 = smem_u32(ems4[2]);
        const uint32_t bb1 = smem_u32(ems4[3]);
        STAGE_EMS(7, bb0)
        STAGE_EMS(6, bb1)

        unsigned mwords[16];
#pragma unroll
        for (int w = 0; w < 16; ++w)
            mwords[w] = __ballot_sync(0xffffffffu, smaskp[w * 32 + j]);

        // row constants: et2[m] = (E[i][2m], E[i][2m+1]), col 25 -> 0
        ull et2[13];
#pragma unroll
        for (int i = 0; i < 13; ++i) {
            float lo = __expf(trans[jc * Ln + 2 * i]);
            float hi = (2 * i + 1 < Ln) ? __expf(trans[jc * Ln + 2 * i + 1]) : 0.f;
            et2[i] = pack2(lo, hi);
        }

        float p = lane_ok ? __expf(end_t[jc]) : 0.f;
        float C = 0.f;
        for (int cc = 0; cc < 4; ++cc) {
            if (cc < 3) asm volatile("cp.async.wait_group 1;" ::: "memory");
            else        asm volatile("cp.async.wait_group 0;" ::: "memory");
            __syncwarp();
            const float* emsb = ems4[2 + (cc & 1)];
            const int ch = 7 - cc;
            const int tbase = ch * 64;

            float emc = emsb[63 * Ln + jc] * lane_okf;
#pragma unroll
            for (int g = 3; g >= 0; --g) {
#pragma unroll
                for (int u = 15; u >= 0; --u) CRF_BSTEP(g * 16 + u, tbase + g * 16 + u)
                CRF_RENORM
            }
            if (cc + 2 < 4) STAGE_EMS(7 - (cc + 2), (cc & 1) ? bb1 : bb0)
        }
        cmb[32 + j] = p;
        if (j == 0) cmbC[1] = C;
    } else {
        // ================= numerator =================
        float numv = 0.f; int msum = 0;
        for (int t = j; t < Tn; t += 32) {
            int m = smaskp[t];
            msum += m;
            if (t == 0)  numv += start_t[lb[0]] + emtagb[0];
            else if (m)  numv += trans[lb[t - 1] * Ln + lb[t]] + emtagb[t];
        }
#pragma unroll
        for (int off = 16; off; off >>= 1) {
            numv += __shfl_xor_sync(0xffffffffu, numv, off);
            msum += __shfl_xor_sync(0xffffffffu, msum, off);
        }
        if (j == 0) numsh[0] = numv + end_t[lb[msum - 1]];
    }
    __syncthreads();

    if (wid == 0) {
        float z = lane_ok ? cmb[j] * cmb[32 + j] : 0.f;
#pragma unroll
        for (int off = 16; off; off >>= 1) z += __shfl_xor_sync(0xffffffffu, z, off);
        if (j == 0) {
            float denom = cmbC[0] + cmbC[1] + __logf(z);
            g_llh[b] = numsh[0] - denom;
            __threadfence();
            int old = atomicAdd(&g_cnt, 1);
            if (old == Bn - 1) {
                __threadfence();
                float s = 0.f;
#pragma unroll 8
                for (int i = 0; i < Bn; ++i) s += __ldcv(&g_llh[i]);
                out[0] = -s * (1.0f / 64.0f);
            }
        }
    }
}

// ---------------------------------------------------------------------------
extern "C" void kernel_launch(void* const* d_in, const int* in_sizes, int n_in,
                              void* d_out, int out_size) {
    const float* X      = (const float*)d_in[0];
    const int*   mask   = (const int*)  d_in[1];
    const int*   labels = (const int*)  d_in[2];
    const float* W      = (const float*)d_in[3];
    const float* bias   = (const float*)d_in[4];
    const float* trans  = (const float*)d_in[5];
    const float* st     = (const float*)d_in[6];
    const float* en     = (const float*)d_in[7];
    float* out = (float*)d_out;

    gemm_kernel<<<512, 128, GSMEM>>>(X, W, bias, labels);
    crf_kernel<<<Bn, 96>>>(mask, labels, trans, st, en, out);
}